// round 3
// baseline (speedup 1.0000x reference)
#include <cuda_runtime.h>
#include <math.h>

// ---------------------------------------------------------------------------
// Packed fp32x2 helpers (Blackwell FFMA2 — only reachable via inline PTX)
// ---------------------------------------------------------------------------
__device__ __forceinline__ unsigned long long pk2(float a, float b) {
    unsigned long long r;
    asm("mov.b64 %0, {%1, %2};" : "=l"(r) : "f"(a), "f"(b));
    return r;
}
__device__ __forceinline__ void fma2(unsigned long long& d,
                                     unsigned long long a, unsigned long long b) {
    asm("fma.rn.f32x2 %0, %1, %2, %0;" : "+l"(d) : "l"(a), "l"(b));
}
__device__ __forceinline__ float2 up2(unsigned long long v) {
    float2 r;
    asm("mov.b64 {%0, %1}, %2;" : "=f"(r.x), "=f"(r.y) : "l"(v));
    return r;
}

// ---------------------------------------------------------------------------
// Scratch buffers (device globals — no allocation allowed)
// ---------------------------------------------------------------------------
__device__ float g_bwt [(size_t)4*512*128*128]; // bwt output / 1x1 result (+bwt in place)
__device__ float g_r1  [(size_t)4*64*128*128];  // relu(conv body1)
__device__ float g_r2  [(size_t)4*512*128*128]; // conv body2
__device__ float g_pool[(size_t)4*2*128*128];
__device__ float g_sal [(size_t)4*128*128];
__device__ float g_m   [4*512];
__device__ float g_cal [4*512];
__device__ float g_wave[(size_t)4*64*256*256];

// ---------------------------------------------------------------------------
// K1: BWT  x(4,64,256,256) -> (4,512,128,128)
// ---------------------------------------------------------------------------
__global__ void bwt_kernel(const float* __restrict__ x, float* __restrict__ o)
{
    int idx = blockIdx.x * 256 + threadIdx.x;
    int j = idx & 127;
    int i = (idx >> 7) & 127;
    int c = (idx >> 14) & 63;
    int b = idx >> 20;
    const float* xp = x + ((size_t)(b*64 + c)*256 + 2*i)*256 + 2*j;
    float2 r0 = *(const float2*)xp;
    float2 r1 = *(const float2*)(xp + 256);
    float x1 = r0.x*0.5f, x3 = r0.y*0.5f, x2 = r1.x*0.5f, x4 = r1.y*0.5f;
    size_t ob = ((size_t)(b*512 + c) << 14) + (i << 7) + j;
    const size_t gs = (size_t)64 << 14;
    o[ob + 0*gs] =  x1 + x2 + x3 + x4;
    o[ob + 1*gs] = -x1 - x2 + x3 + x4;
    o[ob + 2*gs] = -x1 + x2 - x3 + x4;
    o[ob + 3*gs] =  x1 - x2 - x3 + x4;
    o[ob + 4*gs] =  x1 + x2 - x3 - x4;
    o[ob + 5*gs] = -x1 + x2 + x3 - x4;
    o[ob + 6*gs] =  x1 - x2 + x3 - x4;
    o[ob + 7*gs] = -x1 - x2 - x3 - x4;
}

// ---------------------------------------------------------------------------
// Packed 3x3 conv (pad=1). 32x32 spatial tile, 16 cout per block.
// 256 threads = 128 pixel-threads (2 rows x 4 cols each) x 2 co-halves (8 co).
// Weights duplicated into u64 pairs in smem; inner loop is pure FFMA2.
// ---------------------------------------------------------------------------
template<int CIN, int COUT, int HH, bool RELU, bool ADD_OUT>
__global__ __launch_bounds__(256, 2)
void conv3x3p_kernel(const float* __restrict__ in, const float* __restrict__ w,
                     float* out)
{
    constexpr int CCH = 8;     // input channels per smem chunk
    constexpr int COB = 16;    // output channels per block
    __shared__ float sIn[CCH][34][34];
    __shared__ unsigned long long sW[CCH][9][COB];   // (w, w) duplicated pairs

    const int t   = threadIdx.x;
    const int pid = t & 127;
    const int coh = t >> 7;                 // 0/1 co-half
    const int tx  = (pid & 7) * 4;          // 8 groups * 4 px wide = 32
    const int ty  = (pid >> 3) * 2;         // 16 groups * 2 rows   = 32
    const int z   = blockIdx.z;
    const int coT = z % (COUT / COB);
    const int bb  = z / (COUT / COB);
    const int bx0 = blockIdx.x * 32, by0 = blockIdx.y * 32;

    // acc[co][q]: q = row*2 + xpair (xpair 0 -> cols tx,tx+1; 1 -> tx+2,tx+3)
    unsigned long long acc[8][4];
    #pragma unroll
    for (int i = 0; i < 8; ++i)
        #pragma unroll
        for (int q = 0; q < 4; ++q) acc[i][q] = 0ull;

    for (int cc = 0; cc < CIN / CCH; ++cc) {
        const int cb = cc * CCH;
        // stage input halo tile (8 x 34 x 34)
        for (int idx = t; idx < CCH*34*34; idx += 256) {
            int ci = idx / 1156;
            int r  = idx - ci*1156;
            int y  = r / 34;
            int x  = r - y*34;
            int gy = by0 - 1 + y;
            int gx = bx0 - 1 + x;
            float v = 0.f;
            if (gy >= 0 && gy < HH && gx >= 0 && gx < HH)
                v = in[((size_t)(bb*CIN + cb + ci)*HH + gy)*HH + gx];
            sIn[ci][y][x] = v;
        }
        // stage weights, duplicated: sW[ci][k][co] = (w, w)
        for (int idx = t; idx < CCH*9*COB; idx += 256) {
            int ci = idx / 144;
            int r  = idx - ci*144;
            int k  = r >> 4;
            int co = r & 15;
            float v = w[((size_t)(coT*COB + co)*CIN + cb + ci)*9 + k];
            sW[ci][k][co] = pk2(v, v);
        }
        __syncthreads();

        #pragma unroll 1
        for (int ci = 0; ci < CCH; ++ci) {
            // build row pairs pr[r][j] = (patch[r][j], patch[r][j+1]), j=0..4
            unsigned long long pr[4][5];
            #pragma unroll
            for (int r = 0; r < 4; ++r) {
                float2 A = *(const float2*)&sIn[ci][ty + r][tx];
                float2 B = *(const float2*)&sIn[ci][ty + r][tx + 2];
                float2 C = *(const float2*)&sIn[ci][ty + r][tx + 4];
                pr[r][0] = pk2(A.x, A.y);
                pr[r][1] = pk2(A.y, B.x);
                pr[r][2] = pk2(B.x, B.y);
                pr[r][3] = pk2(B.y, C.x);
                pr[r][4] = pk2(C.x, C.y);
            }
            #pragma unroll
            for (int k = 0; k < 9; ++k) {
                const int ky = k / 3, kx = k % 3;
                #pragma unroll
                for (int co = 0; co < 8; ++co) {
                    unsigned long long wv = sW[ci][k][coh*8 + co];
                    fma2(acc[co][0], wv, pr[ky    ][kx    ]);
                    fma2(acc[co][1], wv, pr[ky    ][kx + 2]);
                    fma2(acc[co][2], wv, pr[ky + 1][kx    ]);
                    fma2(acc[co][3], wv, pr[ky + 1][kx + 2]);
                }
            }
        }
        __syncthreads();
    }

    const int oy = by0 + ty, ox = bx0 + tx;
    #pragma unroll
    for (int co = 0; co < 8; ++co) {
        const int cg = coT*COB + coh*8 + co;
        #pragma unroll
        for (int r = 0; r < 2; ++r) {
            float2 a = up2(acc[co][r*2 + 0]);
            float2 b = up2(acc[co][r*2 + 1]);
            float4 v = make_float4(a.x, a.y, b.x, b.y);
            if (RELU) {
                v.x = fmaxf(v.x, 0.f); v.y = fmaxf(v.y, 0.f);
                v.z = fmaxf(v.z, 0.f); v.w = fmaxf(v.w, 0.f);
            }
            size_t oi = ((size_t)(bb*COUT + cg)*HH + oy + r)*HH + ox;
            if (ADD_OUT) {
                float4 p = *(const float4*)(out + oi);
                v.x += p.x; v.y += p.y; v.z += p.z; v.w += p.w;
            }
            *(float4*)(out + oi) = v;
        }
    }
}

// ---------------------------------------------------------------------------
// Packed 1x1 conv as GEMM: 64 cout x 256 pixels per block.
// 256 threads = 32 px-threads (8 px each) x 8 co-threads (8 co each).
//   SALCAL : weight *= cal[ci], output *= sal[pixel]
//   ADD_IN : out += existing out content ("+ x_bwt" in place)
// ---------------------------------------------------------------------------
template<int COUT, int CIN, int HW, bool SALCAL, bool ADD_IN>
__global__ __launch_bounds__(256)
void conv1x1p_kernel(const float* __restrict__ in, const float* __restrict__ w,
                     const float* __restrict__ sal, const float* __restrict__ cal,
                     float* out)
{
    __shared__ __align__(16) float sIn[16][256];
    __shared__ unsigned long long sW[16][64];
    const int t  = threadIdx.x;
    const int tp = t & 31, tc = t >> 5;
    const int p0 = tp * 8, co0 = tc * 8;
    const int pBase  = blockIdx.x * 256;
    const int b      = blockIdx.y;
    const int coBase = blockIdx.z * 64;

    unsigned long long acc[8][4];
    #pragma unroll
    for (int i = 0; i < 8; ++i)
        #pragma unroll
        for (int q = 0; q < 4; ++q) acc[i][q] = 0ull;

    for (int kc = 0; kc < CIN / 16; ++kc) {
        const int kBase = kc * 16;
        #pragma unroll
        for (int i = t; i < 1024; i += 256) {          // 16 x 256 floats as float4
            int k = i >> 6, x4 = i & 63;
            float4 v = *(const float4*)(in + (size_t)(b*CIN + kBase + k)*HW + pBase + x4*4);
            *(float4*)&sIn[k][x4*4] = v;
        }
        #pragma unroll
        for (int i = t; i < 1024; i += 256) {          // 16 x 64 weights, duplicated
            int co = i >> 4, k = i & 15;
            float v = w[(size_t)(coBase + co)*CIN + kBase + k];
            if (SALCAL) v *= cal[b*CIN + kBase + k];
            sW[k][co] = pk2(v, v);
        }
        __syncthreads();
        #pragma unroll
        for (int k = 0; k < 16; ++k) {
            const unsigned long long* vp = (const unsigned long long*)&sIn[k][p0];
            unsigned long long v0 = vp[0], v1 = vp[1], v2 = vp[2], v3 = vp[3];
            #pragma unroll
            for (int co = 0; co < 8; ++co) {
                unsigned long long wv = sW[k][co0 + co];
                fma2(acc[co][0], wv, v0);
                fma2(acc[co][1], wv, v1);
                fma2(acc[co][2], wv, v2);
                fma2(acc[co][3], wv, v3);
            }
        }
        __syncthreads();
    }

    const int pg = pBase + p0;
    float s[8];
    #pragma unroll
    for (int j = 0; j < 8; ++j) s[j] = 1.f;
    if (SALCAL) {
        float4 s0 = *(const float4*)(sal + ((size_t)b)*HW + pg);
        float4 s1 = *(const float4*)(sal + ((size_t)b)*HW + pg + 4);
        s[0]=s0.x; s[1]=s0.y; s[2]=s0.z; s[3]=s0.w;
        s[4]=s1.x; s[5]=s1.y; s[6]=s1.z; s[7]=s1.w;
    }
    #pragma unroll
    for (int co = 0; co < 8; ++co) {
        size_t oi = (size_t)(b*COUT + coBase + co0 + co)*HW + pg;
        float f[8];
        #pragma unroll
        for (int q = 0; q < 4; ++q) {
            float2 u = up2(acc[co][q]);
            f[q*2] = u.x * s[q*2]; f[q*2+1] = u.y * s[q*2+1];
        }
        if (ADD_IN) {
            float4 p0v = *(const float4*)(out + oi);
            float4 p1v = *(const float4*)(out + oi + 4);
            f[0]+=p0v.x; f[1]+=p0v.y; f[2]+=p0v.z; f[3]+=p0v.w;
            f[4]+=p1v.x; f[5]+=p1v.y; f[6]+=p1v.z; f[7]+=p1v.w;
        }
        *(float4*)(out + oi)     = make_float4(f[0], f[1], f[2], f[3]);
        *(float4*)(out + oi + 4) = make_float4(f[4], f[5], f[6], f[7]);
    }
}

// ---------------------------------------------------------------------------
// K4: channel max/mean pooling over 512 channels (float4-vectorized)
// ---------------------------------------------------------------------------
__global__ void chanpool_kernel(const float* __restrict__ r2, float* __restrict__ pool)
{
    int p4 = blockIdx.x * 256 + threadIdx.x;      // 4096 float4 groups per batch
    int b  = blockIdx.y;
    const float* base = r2 + (((size_t)b*512) << 14) + p4*4;
    float4 mx = make_float4(-3.4e38f, -3.4e38f, -3.4e38f, -3.4e38f);
    float4 s  = make_float4(0.f, 0.f, 0.f, 0.f);
    #pragma unroll 4
    for (int c = 0; c < 512; ++c) {
        float4 v = *(const float4*)(base + ((size_t)c << 14));
        mx.x = fmaxf(mx.x, v.x); mx.y = fmaxf(mx.y, v.y);
        mx.z = fmaxf(mx.z, v.z); mx.w = fmaxf(mx.w, v.w);
        s.x += v.x; s.y += v.y; s.z += v.z; s.w += v.w;
    }
    const float inv = 1.f/512.f;
    s.x *= inv; s.y *= inv; s.z *= inv; s.w *= inv;
    *(float4*)(pool + (((size_t)(b*2    )) << 14) + p4*4) = mx;
    *(float4*)(pool + (((size_t)(b*2 + 1)) << 14) + p4*4) = s;
}

// ---------------------------------------------------------------------------
// K5: 5x5 conv (2->1, pad 2) + sigmoid -> spatial attention map
// ---------------------------------------------------------------------------
__global__ void salconv_kernel(const float* __restrict__ pool,
                               const float* __restrict__ wsal,
                               float* __restrict__ sal)
{
    int p = blockIdx.x * 256 + threadIdx.x;
    int b = blockIdx.y;
    int y = p >> 7, x = p & 127;
    float a = 0.f;
    #pragma unroll
    for (int c = 0; c < 2; ++c) {
        const float* pp = pool + (((size_t)(b*2 + c)) << 14);
        #pragma unroll
        for (int ky = 0; ky < 5; ++ky) {
            int iy = y + ky - 2;
            if (iy < 0 || iy >= 128) continue;
            #pragma unroll
            for (int kx = 0; kx < 5; ++kx) {
                int ix = x + kx - 2;
                if (ix < 0 || ix >= 128) continue;
                a += wsal[c*25 + ky*5 + kx] * pp[(iy << 7) + ix];
            }
        }
    }
    sal[(((size_t)b) << 14) + p] = 1.f / (1.f + expf(-a));
}

// ---------------------------------------------------------------------------
// K6: weighted channel mean  m[b,c] = mean_p( r2[b,c,p] * sal[b,p] )
// ---------------------------------------------------------------------------
__global__ void wmean_kernel(const float* __restrict__ r2,
                             const float* __restrict__ sal,
                             float* __restrict__ m)
{
    int c = blockIdx.x, b = blockIdx.y;
    const float* r = r2 + (((size_t)(b*512 + c)) << 14);
    const float* s = sal + (((size_t)b) << 14);
    float sum = 0.f;
    for (int i = threadIdx.x; i < 4096; i += 256) {
        float4 rv = *(const float4*)(r + i*4);
        float4 sv = *(const float4*)(s + i*4);
        sum += rv.x*sv.x + rv.y*sv.y + rv.z*sv.z + rv.w*sv.w;
    }
    #pragma unroll
    for (int o = 16; o > 0; o >>= 1) sum += __shfl_xor_sync(0xffffffffu, sum, o);
    __shared__ float red[8];
    if ((threadIdx.x & 31) == 0) red[threadIdx.x >> 5] = sum;
    __syncthreads();
    if (threadIdx.x == 0) {
        float tot = 0.f;
        #pragma unroll
        for (int i = 0; i < 8; ++i) tot += red[i];
        m[b*512 + c] = tot * (1.f/16384.f);
    }
}

// ---------------------------------------------------------------------------
// K7: channel-attention MLP: cal = sigmoid(W2 * relu(W1 * m))
// ---------------------------------------------------------------------------
__global__ void calmlp_kernel(const float* __restrict__ m,
                              const float* __restrict__ wca1,
                              const float* __restrict__ wca2,
                              float* __restrict__ cal)
{
    int b = blockIdx.x;
    __shared__ float sm[512];
    __shared__ float sy1[32];
    for (int i = threadIdx.x; i < 512; i += 256) sm[i] = m[b*512 + i];
    __syncthreads();
    if (threadIdx.x < 32) {
        float a = 0.f;
        for (int c = 0; c < 512; ++c) a += wca1[threadIdx.x*512 + c] * sm[c];
        sy1[threadIdx.x] = fmaxf(a, 0.f);
    }
    __syncthreads();
    for (int c = threadIdx.x; c < 512; c += 256) {
        float a = 0.f;
        #pragma unroll
        for (int j = 0; j < 32; ++j) a += wca2[c*32 + j] * sy1[j];
        cal[b*512 + c] = 1.f / (1.f + expf(-a));
    }
}

// ---------------------------------------------------------------------------
// K9: IBWT  (4,512,128,128) -> (4,64,256,256)
// ---------------------------------------------------------------------------
__global__ void ibwt_kernel(const float* __restrict__ r, float* __restrict__ o)
{
    int idx = blockIdx.x * 256 + threadIdx.x;
    int j = idx & 127;
    int i = (idx >> 7) & 127;
    int c = (idx >> 14) & 63;
    int b = idx >> 20;
    size_t base = ((size_t)(b*512 + c) << 14) + (i << 7) + j;
    const size_t gs = (size_t)64 << 14;
    float x1 = r[base       ]*0.5f, x2 = r[base +   gs]*0.5f;
    float x3 = r[base + 2*gs]*0.5f, x4 = r[base + 3*gs]*0.5f;
    float x5 = r[base + 4*gs]*0.5f, x6 = r[base + 5*gs]*0.5f;
    float x7 = r[base + 6*gs]*0.5f, x8 = r[base + 7*gs]*0.5f;
    float a00 = x1 - x2 - x3 + x4 + x5 - x6 + x7 - x8;
    float a10 = x1 - x2 + x3 - x4 - x5 + x6 - x7 + x8;
    float a01 = x1 + x2 - x3 - x4 - x5 - x6 + x7 + x8;
    float a11 = x1 + x2 + x3 + x4 + x5 + x6 + x7 + x8;
    float* op = o + ((size_t)(b*64 + c)*256 + 2*i)*256 + 2*j;
    *(float2*)op         = make_float2(a00, a01);
    *(float2*)(op + 256) = make_float2(a10, a11);
}

// ---------------------------------------------------------------------------
// Launch
// ---------------------------------------------------------------------------
extern "C" void kernel_launch(void* const* d_in, const int* in_sizes, int n_in,
                              void* d_out, int out_size)
{
    const float* x       = (const float*)d_in[0];
    const float* w_body1 = (const float*)d_in[1];
    const float* w_body2 = (const float*)d_in[2];
    const float* w_sal   = (const float*)d_in[3];
    const float* w_ca1   = (const float*)d_in[4];
    const float* w_ca2   = (const float*)d_in[5];
    const float* w_1x1   = (const float*)d_in[6];
    const float* w_3x3   = (const float*)d_in[7];
    const float* w_final = (const float*)d_in[8];
    float* out = (float*)d_out;

    float *bwt, *r1, *r2, *pool, *sal, *m, *cal, *wave;
    cudaGetSymbolAddress((void**)&bwt,  g_bwt);
    cudaGetSymbolAddress((void**)&r1,   g_r1);
    cudaGetSymbolAddress((void**)&r2,   g_r2);
    cudaGetSymbolAddress((void**)&pool, g_pool);
    cudaGetSymbolAddress((void**)&sal,  g_sal);
    cudaGetSymbolAddress((void**)&m,    g_m);
    cudaGetSymbolAddress((void**)&cal,  g_cal);
    cudaGetSymbolAddress((void**)&wave, g_wave);

    // 1) BWT
    bwt_kernel<<<16384, 256>>>(x, bwt);
    // 2) conv body1 3x3 (512 -> 64) + relu
    conv3x3p_kernel<512, 64, 128, true, false><<<dim3(4,4,16), 256>>>(bwt, w_body1, r1);
    // 3) conv body2 3x3 (64 -> 512)
    conv3x3p_kernel<64, 512, 128, false, false><<<dim3(4,4,128), 256>>>(r1, w_body2, r2);
    // 4) channel pooling (max/avg)
    chanpool_kernel<<<dim3(16,4), 256>>>(r2, pool);
    // 5) 5x5 conv + sigmoid -> sal map
    salconv_kernel<<<dim3(64,4), 256>>>(pool, w_sal, sal);
    // 6) weighted channel means
    wmean_kernel<<<dim3(512,4), 256>>>(r2, sal, m);
    // 7) channel attention MLP
    calmlp_kernel<<<4, 256>>>(m, w_ca1, w_ca2, cal);
    // 8) 1x1 conv (512->512), cal folded into weights, sal in epilogue, +x_bwt in place
    conv1x1p_kernel<512, 512, 16384, true, true><<<dim3(64,4,8), 256>>>(r2, w_1x1, sal, cal, bwt);
    // 9) IBWT
    ibwt_kernel<<<16384, 256>>>(bwt, wave);
    // 10) final 1x1 conv of residual -> out
    conv1x1p_kernel<64, 64, 65536, false, false><<<dim3(256,4,1), 256>>>(x, w_final, nullptr, nullptr, out);
    // 11) final 3x3 conv + relu, added onto out
    conv3x3p_kernel<64, 64, 256, true, true><<<dim3(8,8,16), 256>>>(wave, w_3x3, out);
}

// round 5
// speedup vs baseline: 1.5615x; 1.5615x over previous
#include <cuda_runtime.h>
#include <cuda_bf16.h>
#include <math.h>
#include <stdint.h>

// ===========================================================================
// mma.sync m16n8k16 row.col bf16*bf16 -> f32 (compute_80+, works on sm_103)
// ===========================================================================
__device__ __forceinline__ void mma_bf16(float* c, const uint32_t* a, const uint32_t* b)
{
    asm volatile(
        "mma.sync.aligned.m16n8k16.row.col.f32.bf16.bf16.f32 "
        "{%0,%1,%2,%3}, {%4,%5,%6,%7}, {%8,%9}, {%0,%1,%2,%3};"
        : "+f"(c[0]), "+f"(c[1]), "+f"(c[2]), "+f"(c[3])
        : "r"(a[0]), "r"(a[1]), "r"(a[2]), "r"(a[3]), "r"(b[0]), "r"(b[1]));
}

// ===========================================================================
// Scratch buffers
// ===========================================================================
__device__ float g_bwt [(size_t)4*512*128*128];
__device__ float g_r1  [(size_t)4*64*128*128];
__device__ float g_r2  [(size_t)4*512*128*128];
__device__ float g_pool[(size_t)4*2*128*128];
__device__ float g_sal [(size_t)4*128*128];
__device__ float g_m   [4*512];
__device__ float g_cal [4*512];
__device__ float g_wave[(size_t)4*64*256*256];

// ===========================================================================
// K1: BWT  x(4,64,256,256) -> (4,512,128,128)
// ===========================================================================
__global__ void bwt_kernel(const float* __restrict__ x, float* __restrict__ o)
{
    int idx = blockIdx.x * 256 + threadIdx.x;
    int j = idx & 127;
    int i = (idx >> 7) & 127;
    int c = (idx >> 14) & 63;
    int b = idx >> 20;
    const float* xp = x + ((size_t)(b*64 + c)*256 + 2*i)*256 + 2*j;
    float2 r0 = *(const float2*)xp;
    float2 r1 = *(const float2*)(xp + 256);
    float x1 = r0.x*0.5f, x3 = r0.y*0.5f, x2 = r1.x*0.5f, x4 = r1.y*0.5f;
    size_t ob = ((size_t)(b*512 + c) << 14) + (i << 7) + j;
    const size_t gs = (size_t)64 << 14;
    o[ob + 0*gs] =  x1 + x2 + x3 + x4;
    o[ob + 1*gs] = -x1 - x2 + x3 + x4;
    o[ob + 2*gs] = -x1 + x2 - x3 + x4;
    o[ob + 3*gs] =  x1 - x2 - x3 + x4;
    o[ob + 4*gs] =  x1 + x2 - x3 - x4;
    o[ob + 5*gs] = -x1 + x2 + x3 - x4;
    o[ob + 6*gs] =  x1 - x2 + x3 - x4;
    o[ob + 7*gs] = -x1 - x2 - x3 - x4;
}

// ===========================================================================
// Unified implicit-GEMM conv via mma.sync (KS=1 or 3), bf16 3-term split.
// CTA: 128 pixels (8 rows x 16 cols) x 64 couts, 128 threads (4 warps).
// Warp tile: m32 x n64. K loop: 16 input channels per chunk x KS*KS taps.
//   D = Ahi*Bhi + Ahi*Blo + Alo*Bhi   (f32 accumulate)
//   SALCAL : fold cal[ci] into weights, multiply output by sal[pixel]
//   ADD_OUT: out[..] += result
// ===========================================================================
template<int CIN, int COUT, int H, int KS, bool RELU, bool ADD_OUT, bool SALCAL>
__global__ __launch_bounds__(128)
void mmaconv_kernel(const float* __restrict__ in, const float* __restrict__ w,
                    const float* __restrict__ sal, const float* __restrict__ cal,
                    float* out)
{
    constexpr int KS2 = KS*KS;
    constexpr int PAD = KS/2;
    constexpr int HR  = 8 + KS - 1;
    constexpr int HC  = 16 + KS - 1;
    constexpr int HEL = HR*HC;

    __shared__ __align__(16) unsigned short sHhi[HEL*16];
    __shared__ __align__(16) unsigned short sHlo[HEL*16];
    __shared__ __align__(16) unsigned short sWhi[KS2*64*16];
    __shared__ __align__(16) unsigned short sWlo[KS2*64*16];

    const int t    = threadIdx.x;
    const int lane = t & 31, wid = t >> 5;
    const int g    = lane >> 2;            // fragment row group
    const int c0   = (lane & 3) * 2;       // fragment col pair base
    const int bx0  = blockIdx.x * 16;
    const int by0  = blockIdx.y * 8;
    const int z    = blockIdx.z;
    const int coT  = z % (COUT/64);
    const int b    = z / (COUT/64);
    const int warp_m = wid * 32;

    const uint32_t* Hh = (const uint32_t*)sHhi;
    const uint32_t* Hl = (const uint32_t*)sHlo;
    const uint32_t* Wh = (const uint32_t*)sWhi;
    const uint32_t* Wl = (const uint32_t*)sWlo;

    float acc[2][8][4];
    #pragma unroll
    for (int mf = 0; mf < 2; ++mf)
        #pragma unroll
        for (int nf = 0; nf < 8; ++nf)
            #pragma unroll
            for (int q = 0; q < 4; ++q) acc[mf][nf][q] = 0.f;

    #pragma unroll 1
    for (int cc = 0; cc < CIN/16; ++cc) {
        const int cb = cc * 16;

        // ---- stage input halo (hi/lo split), coalesced over pixels ----
        for (int idx = t; idx < 16*HEL; idx += 128) {
            int ci  = idx / HEL;
            int pix = idx - ci*HEL;
            int py  = pix / HC;
            int px  = pix - py*HC;
            int gy  = by0 + py - PAD;
            int gx  = bx0 + px - PAD;
            float v = 0.f;
            if (gy >= 0 && gy < H && gx >= 0 && gx < H)
                v = in[((size_t)(b*CIN + cb + ci)*H + gy)*H + gx];
            __nv_bfloat16 h = __float2bfloat16_rn(v);
            __nv_bfloat16 l = __float2bfloat16_rn(v - __bfloat162float(h));
            sHhi[pix*16 + ci] = __bfloat16_as_ushort(h);
            sHlo[pix*16 + ci] = __bfloat16_as_ushort(l);
        }
        // ---- stage weights (hi/lo, optional cal fold) ----
        for (int idx = t; idx < 64*16*KS2; idx += 128) {
            int co  = idx / (16*KS2);
            int r   = idx - co*(16*KS2);
            int ci  = r / KS2;
            int tap = r - ci*KS2;
            float v = w[((size_t)(coT*64 + co)*CIN + cb + ci)*KS2 + tap];
            if (SALCAL) v *= __ldg(&cal[b*CIN + cb + ci]);
            __nv_bfloat16 h = __float2bfloat16_rn(v);
            __nv_bfloat16 l = __float2bfloat16_rn(v - __bfloat162float(h));
            sWhi[(tap*64 + co)*16 + ci] = __bfloat16_as_ushort(h);
            sWlo[(tap*64 + co)*16 + ci] = __bfloat16_as_ushort(l);
        }
        __syncthreads();

        for (int tap = 0; tap < KS2; ++tap) {
            const int dy = tap / KS, dx = tap - dy*KS;

            // B fragments for all 8 n-frags (hi + lo)
            uint32_t bh[8][2], bl[8][2];
            #pragma unroll
            for (int nf = 0; nf < 8; ++nf) {
                int wb = (tap*64 + nf*8 + g)*8 + (c0 >> 1);
                bh[nf][0] = Wh[wb]; bh[nf][1] = Wh[wb + 4];
                bl[nf][0] = Wl[wb]; bl[nf][1] = Wl[wb + 4];
            }
            #pragma unroll
            for (int mf = 0; mf < 2; ++mf) {
                const int p  = warp_m + mf*16 + g;
                const int p8 = p + 8;
                const int a0 = (((p  >> 4) + dy)*HC + (p  & 15) + dx)*8 + (c0 >> 1);
                const int a8 = (((p8 >> 4) + dy)*HC + (p8 & 15) + dx)*8 + (c0 >> 1);
                uint32_t ah[4] = {Hh[a0], Hh[a8], Hh[a0 + 4], Hh[a8 + 4]};
                uint32_t al[4] = {Hl[a0], Hl[a8], Hl[a0 + 4], Hl[a8 + 4]};
                #pragma unroll
                for (int nf = 0; nf < 8; ++nf) {
                    mma_bf16(acc[mf][nf], ah, bh[nf]);
                    mma_bf16(acc[mf][nf], ah, bl[nf]);
                    mma_bf16(acc[mf][nf], al, bh[nf]);
                }
            }
        }
        __syncthreads();
    }

    // ---- epilogue ----
    #pragma unroll
    for (int mf = 0; mf < 2; ++mf) {
        const int p   = warp_m + mf*16 + g;
        const int p8  = p + 8;
        const int gy0 = by0 + (p  >> 4), gx0 = bx0 + (p  & 15);
        const int gy8 = by0 + (p8 >> 4), gx8 = bx0 + (p8 & 15);
        float s0 = 1.f, s8 = 1.f;
        if (SALCAL) {
            s0 = sal[((size_t)b*H + gy0)*H + gx0];
            s8 = sal[((size_t)b*H + gy8)*H + gx8];
        }
        #pragma unroll
        for (int nf = 0; nf < 8; ++nf) {
            const int co = coT*64 + nf*8 + c0;
            size_t o0 = ((size_t)(b*COUT + co)*H + gy0)*H + gx0;
            size_t o1 = o0 + (size_t)H*H;
            size_t o2 = ((size_t)(b*COUT + co)*H + gy8)*H + gx8;
            size_t o3 = o2 + (size_t)H*H;
            float v0 = acc[mf][nf][0]*s0, v1 = acc[mf][nf][1]*s0;
            float v2 = acc[mf][nf][2]*s8, v3 = acc[mf][nf][3]*s8;
            if (RELU) {
                v0 = fmaxf(v0, 0.f); v1 = fmaxf(v1, 0.f);
                v2 = fmaxf(v2, 0.f); v3 = fmaxf(v3, 0.f);
            }
            if (ADD_OUT) { v0 += out[o0]; v1 += out[o1]; v2 += out[o2]; v3 += out[o3]; }
            out[o0] = v0; out[o1] = v1; out[o2] = v2; out[o3] = v3;
        }
    }
}

// ===========================================================================
// Scalar 1x1 conv GEMM — used for the small residual 64x64 conv
// ===========================================================================
template<int COUT, int CIN, int HW>
__global__ __launch_bounds__(256)
void conv1x1_kernel(const float* __restrict__ in, const float* __restrict__ w,
                    float* out)
{
    __shared__ __align__(16) float sIn[16][128];
    __shared__ __align__(16) float sW [16][64];
    const int t  = threadIdx.x;
    const int tp = t & 31, tc = t >> 5;
    const int p0 = tp * 4, co0 = tc * 8;
    const int pBase  = blockIdx.x * 128;
    const int b      = blockIdx.y;
    const int coBase = blockIdx.z * 64;

    float acc[8][4];
    #pragma unroll
    for (int i = 0; i < 8; ++i) { acc[i][0]=acc[i][1]=acc[i][2]=acc[i][3]=0.f; }

    for (int kc = 0; kc < CIN / 16; ++kc) {
        const int kBase = kc * 16;
        #pragma unroll
        for (int i = t; i < 512; i += 256) {
            int k = i >> 5, x4 = i & 31;
            float4 v = *(const float4*)(in + (size_t)(b*CIN + kBase + k)*HW + pBase + x4*4);
            *(float4*)&sIn[k][x4*4] = v;
        }
        #pragma unroll
        for (int i = t; i < 1024; i += 256) {
            int co = i >> 4, k = i & 15;
            sW[k][co] = w[(size_t)(coBase + co)*CIN + kBase + k];
        }
        __syncthreads();
        #pragma unroll
        for (int k = 0; k < 16; ++k) {
            float4 v  = *(const float4*)&sIn[k][p0];
            float4 wl = *(const float4*)&sW[k][co0];
            float4 wh = *(const float4*)&sW[k][co0 + 4];
            float va[4] = {v.x, v.y, v.z, v.w};
            float wa[8] = {wl.x, wl.y, wl.z, wl.w, wh.x, wh.y, wh.z, wh.w};
            #pragma unroll
            for (int co = 0; co < 8; ++co)
                #pragma unroll
                for (int j = 0; j < 4; ++j)
                    acc[co][j] += wa[co] * va[j];
        }
        __syncthreads();
    }

    const int pg = pBase + p0;
    #pragma unroll
    for (int co = 0; co < 8; ++co) {
        size_t oi = (size_t)(b*COUT + coBase + co0 + co)*HW + pg;
        *(float4*)(out + oi) = make_float4(acc[co][0], acc[co][1], acc[co][2], acc[co][3]);
    }
}

// ===========================================================================
// Attention glue kernels
// ===========================================================================
__global__ void chanpool_kernel(const float* __restrict__ r2, float* __restrict__ pool)
{
    int p = blockIdx.x * 256 + threadIdx.x;
    int b = blockIdx.y;
    const float* base = r2 + (((size_t)b*512) << 14) + p;
    float mx = -3.4e38f, s = 0.f;
    #pragma unroll 8
    for (int c = 0; c < 512; ++c) {
        float v = base[(size_t)c << 14];
        mx = fmaxf(mx, v);
        s += v;
    }
    pool[(((size_t)(b*2    )) << 14) + p] = mx;
    pool[(((size_t)(b*2 + 1)) << 14) + p] = s * (1.f/512.f);
}

__global__ void salconv_kernel(const float* __restrict__ pool,
                               const float* __restrict__ wsal,
                               float* __restrict__ sal)
{
    int p = blockIdx.x * 256 + threadIdx.x;
    int b = blockIdx.y;
    int y = p >> 7, x = p & 127;
    float a = 0.f;
    #pragma unroll
    for (int c = 0; c < 2; ++c) {
        const float* pp = pool + (((size_t)(b*2 + c)) << 14);
        #pragma unroll
        for (int ky = 0; ky < 5; ++ky) {
            int iy = y + ky - 2;
            if (iy < 0 || iy >= 128) continue;
            #pragma unroll
            for (int kx = 0; kx < 5; ++kx) {
                int ix = x + kx - 2;
                if (ix < 0 || ix >= 128) continue;
                a += wsal[c*25 + ky*5 + kx] * pp[(iy << 7) + ix];
            }
        }
    }
    sal[(((size_t)b) << 14) + p] = 1.f / (1.f + expf(-a));
}

__global__ void wmean_kernel(const float* __restrict__ r2,
                             const float* __restrict__ sal,
                             float* __restrict__ m)
{
    int c = blockIdx.x, b = blockIdx.y;
    const float* r = r2 + (((size_t)(b*512 + c)) << 14);
    const float* s = sal + (((size_t)b) << 14);
    float sum = 0.f;
    for (int i = threadIdx.x; i < 4096; i += 256) {
        float4 rv = *(const float4*)(r + i*4);
        float4 sv = *(const float4*)(s + i*4);
        sum += rv.x*sv.x + rv.y*sv.y + rv.z*sv.z + rv.w*sv.w;
    }
    #pragma unroll
    for (int o = 16; o > 0; o >>= 1) sum += __shfl_xor_sync(0xffffffffu, sum, o);
    __shared__ float red[8];
    if ((threadIdx.x & 31) == 0) red[threadIdx.x >> 5] = sum;
    __syncthreads();
    if (threadIdx.x == 0) {
        float tot = 0.f;
        #pragma unroll
        for (int i = 0; i < 8; ++i) tot += red[i];
        m[b*512 + c] = tot * (1.f/16384.f);
    }
}

__global__ void calmlp_kernel(const float* __restrict__ m,
                              const float* __restrict__ wca1,
                              const float* __restrict__ wca2,
                              float* __restrict__ cal)
{
    int b = blockIdx.x;
    __shared__ float sm[512];
    __shared__ float sy1[32];
    for (int i = threadIdx.x; i < 512; i += 256) sm[i] = m[b*512 + i];
    __syncthreads();
    if (threadIdx.x < 32) {
        float a = 0.f;
        for (int c = 0; c < 512; ++c) a += wca1[threadIdx.x*512 + c] * sm[c];
        sy1[threadIdx.x] = fmaxf(a, 0.f);
    }
    __syncthreads();
    for (int c = threadIdx.x; c < 512; c += 256) {
        float a = 0.f;
        #pragma unroll
        for (int j = 0; j < 32; ++j) a += wca2[c*32 + j] * sy1[j];
        cal[b*512 + c] = 1.f / (1.f + expf(-a));
    }
}

// ===========================================================================
// K9: IBWT
// ===========================================================================
__global__ void ibwt_kernel(const float* __restrict__ r, float* __restrict__ o)
{
    int idx = blockIdx.x * 256 + threadIdx.x;
    int j = idx & 127;
    int i = (idx >> 7) & 127;
    int c = (idx >> 14) & 63;
    int b = idx >> 20;
    size_t base = ((size_t)(b*512 + c) << 14) + (i << 7) + j;
    const size_t gs = (size_t)64 << 14;
    float x1 = r[base       ]*0.5f, x2 = r[base +   gs]*0.5f;
    float x3 = r[base + 2*gs]*0.5f, x4 = r[base + 3*gs]*0.5f;
    float x5 = r[base + 4*gs]*0.5f, x6 = r[base + 5*gs]*0.5f;
    float x7 = r[base + 6*gs]*0.5f, x8 = r[base + 7*gs]*0.5f;
    float a00 = x1 - x2 - x3 + x4 + x5 - x6 + x7 - x8;
    float a10 = x1 - x2 + x3 - x4 - x5 + x6 - x7 + x8;
    float a01 = x1 + x2 - x3 - x4 - x5 - x6 + x7 + x8;
    float a11 = x1 + x2 + x3 + x4 + x5 + x6 + x7 + x8;
    float* op = o + ((size_t)(b*64 + c)*256 + 2*i)*256 + 2*j;
    *(float2*)op         = make_float2(a00, a01);
    *(float2*)(op + 256) = make_float2(a10, a11);
}

// ===========================================================================
// Launch
// ===========================================================================
extern "C" void kernel_launch(void* const* d_in, const int* in_sizes, int n_in,
                              void* d_out, int out_size)
{
    const float* x       = (const float*)d_in[0];
    const float* w_body1 = (const float*)d_in[1];
    const float* w_body2 = (const float*)d_in[2];
    const float* w_sal   = (const float*)d_in[3];
    const float* w_ca1   = (const float*)d_in[4];
    const float* w_ca2   = (const float*)d_in[5];
    const float* w_1x1   = (const float*)d_in[6];
    const float* w_3x3   = (const float*)d_in[7];
    const float* w_final = (const float*)d_in[8];
    float* out = (float*)d_out;

    float *bwt, *r1, *r2, *pool, *sal, *m, *cal, *wave;
    cudaGetSymbolAddress((void**)&bwt,  g_bwt);
    cudaGetSymbolAddress((void**)&r1,   g_r1);
    cudaGetSymbolAddress((void**)&r2,   g_r2);
    cudaGetSymbolAddress((void**)&pool, g_pool);
    cudaGetSymbolAddress((void**)&sal,  g_sal);
    cudaGetSymbolAddress((void**)&m,    g_m);
    cudaGetSymbolAddress((void**)&cal,  g_cal);
    cudaGetSymbolAddress((void**)&wave, g_wave);

    // 1) BWT
    bwt_kernel<<<16384, 256>>>(x, bwt);
    // 2) body1 3x3 (512 -> 64) + relu   [tensor]
    mmaconv_kernel<512, 64, 128, 3, true, false, false>
        <<<dim3(8,16,4), 128>>>(bwt, w_body1, nullptr, nullptr, r1);
    // 3) body2 3x3 (64 -> 512)          [tensor]
    mmaconv_kernel<64, 512, 128, 3, false, false, false>
        <<<dim3(8,16,32), 128>>>(r1, w_body2, nullptr, nullptr, r2);
    // 4) channel pooling
    chanpool_kernel<<<dim3(64,4), 256>>>(r2, pool);
    // 5) 5x5 conv + sigmoid -> sal
    salconv_kernel<<<dim3(64,4), 256>>>(pool, w_sal, sal);
    // 6) weighted channel means
    wmean_kernel<<<dim3(512,4), 256>>>(r2, sal, m);
    // 7) channel attention MLP
    calmlp_kernel<<<4, 256>>>(m, w_ca1, w_ca2, cal);
    // 8) 1x1 conv (512->512): cal folded, sal epilogue, += x_bwt  [tensor]
    mmaconv_kernel<512, 512, 128, 1, false, true, true>
        <<<dim3(8,16,32), 128>>>(r2, w_1x1, sal, cal, bwt);
    // 9) IBWT
    ibwt_kernel<<<16384, 256>>>(bwt, wave);
    // 10) residual 1x1 conv -> out (scalar, small)
    conv1x1_kernel<64, 64, 65536><<<dim3(512,4,1), 256>>>(x, w_final, out);
    // 11) final 3x3 conv (64->64) + relu, added onto out  [tensor]
    mmaconv_kernel<64, 64, 256, 3, true, true, false>
        <<<dim3(16,32,4), 128>>>(wave, w_3x3, nullptr, nullptr, out);
}